// round 17
// baseline (speedup 1.0000x reference)
#include <cuda_runtime.h>
#include <cuda_fp16.h>
#include <cstdint>
#include <math.h>

// Problem constants
#define BB     8
#define TLEN   2048
#define HIDD   1024
#define NHH    16
#define MDD    16
#define BT     (BB * TLEN)          // 16384 rows
#define N1     (NHH * MDD * MDD)    // 4096
#define K2D    (NHH * MDD * 2)      // 512

// ---------------------------------------------------------------------------
// Scratch (device globals — no allocation allowed)
// ---------------------------------------------------------------------------
__device__ float  g_m[(size_t)BT * N1];               // scan layout [s][t][256] (UNNORMALIZED)
__device__ __half g_ah[(size_t)BT * HIDD];            // hs hi
__device__ __half g_al[(size_t)BT * HIDD];            // hs lo (unscaled)
__device__ __half g_bh[(size_t)N1 * HIDD];            // W_mat^T hi  [n][k]
__device__ __half g_bl[(size_t)N1 * HIDD];            // W_mat^T lo  [n][k]
__device__ __half g_xh[(size_t)BT * K2D];             // scan out hi
__device__ __half g_xl[(size_t)BT * K2D];             // scan out lo
__device__ __half g_wh[(size_t)HIDD * K2D];           // W_out^T hi [n][k]
__device__ __half g_wl[(size_t)HIDD * K2D];           // W_out^T lo [n][k]

// ---------------------------------------------------------------------------
// Helpers
// ---------------------------------------------------------------------------
__device__ __forceinline__ uint32_t smem_u32(const void* p) {
    uint32_t a;
    asm("{ .reg .u64 t; cvta.to.shared.u64 t, %1; cvt.u32.u64 %0, t; }" : "=r"(a) : "l"(p));
    return a;
}
#define CP_ASYNC16(dst, src) \
    asm volatile("cp.async.cg.shared.global [%0], [%1], 16;\n" :: "r"(dst), "l"(src) : "memory")
#define CP_COMMIT()  asm volatile("cp.async.commit_group;\n" ::: "memory")
#define CP_WAIT1()   asm volatile("cp.async.wait_group 1;\n" ::: "memory")
#define CP_WAIT11()  asm volatile("cp.async.wait_group 11;\n" ::: "memory")

__device__ __forceinline__ void ldsm_x4(uint32_t& r0, uint32_t& r1, uint32_t& r2,
                                        uint32_t& r3, uint32_t addr) {
    asm volatile("ldmatrix.sync.aligned.m8n8.x4.shared.b16 {%0,%1,%2,%3}, [%4];"
                 : "=r"(r0), "=r"(r1), "=r"(r2), "=r"(r3) : "r"(addr));
}
__device__ __forceinline__ void mma_f16(float* c, const uint32_t* a, const uint32_t* b) {
    asm volatile(
        "mma.sync.aligned.m16n8k16.row.col.f32.f16.f16.f32 "
        "{%0,%1,%2,%3}, {%4,%5,%6,%7}, {%8,%9}, {%0,%1,%2,%3};"
        : "+f"(c[0]), "+f"(c[1]), "+f"(c[2]), "+f"(c[3])
        : "r"(a[0]), "r"(a[1]), "r"(a[2]), "r"(a[3]), "r"(b[0]), "r"(b[1]));
}
__device__ __forceinline__ uint32_t swz64(uint32_t off) { return off ^ ((off >> 3) & 0x30); } // SW64

__device__ __forceinline__ void split_f16(float a, __half& h, __half& l) {
    h = __float2half_rn(a);
    l = __float2half_rn(a - __half2float(h));
}

// ---------------------------------------------------------------------------
// Conversion kernels
// ---------------------------------------------------------------------------
struct alignas(8) h4 { __half v[4]; };

__global__ __launch_bounds__(256)
void convA_kernel(const float* __restrict__ x, __half* __restrict__ hi,
                  __half* __restrict__ lo)
{
    const int i = blockIdx.x * blockDim.x + threadIdx.x;
    float4 v = ((const float4*)x)[i];
    h4 h, l;
    float a[4] = {v.x, v.y, v.z, v.w};
#pragma unroll
    for (int j = 0; j < 4; j++) split_f16(a[j], h.v[j], l.v[j]);
    ((h4*)hi)[i] = h;
    ((h4*)lo)[i] = l;
}

// Transpose W (KR x NC, row-major) -> [n][k] fp16 hi/lo
__global__ __launch_bounds__(1024)
void convW_kernel(const float* __restrict__ W, __half* __restrict__ wh,
                  __half* __restrict__ wl, int KR, int NC)
{
    __shared__ float tile[32][33];
    const int n_in = blockIdx.x * 32 + threadIdx.x;
    const int k_in = blockIdx.y * 32 + threadIdx.y;
    tile[threadIdx.y][threadIdx.x] = W[(size_t)k_in * NC + n_in];
    __syncthreads();
    const int n_out = blockIdx.x * 32 + threadIdx.y;
    const int k_out = blockIdx.y * 32 + threadIdx.x;
    const float v = tile[threadIdx.x][threadIdx.y];
    __half h, l;
    split_f16(v, h, l);
    const size_t o = (size_t)n_out * KR + k_out;
    wh[o] = h;
    wl[o] = l;
}

// ---------------------------------------------------------------------------
// FUSED-CHUNK HMMA GEMM (best known):
//   D = Ah*Bl + Al*Bh + Ah*Bh   [+ bias]
// CTA 128x128, 8 warps (2m x 4n), SW64 swizzle, 3-stage ring, 2 CTAs/SM.
// ---------------------------------------------------------------------------
#define CH_K     32                         // halfs per chunk
#define TILE_B   8192                       // 128 rows * 64 bytes
#define ST_B     (4 * TILE_B)               // 32KB per stage (Ah,Al,Bh,Bl)
#define G_SMEM   (1024 + 3 * ST_B)

template <bool PERM, bool GELU, int KDIM, int NDIM>
__global__ __launch_bounds__(256, 2)
void gemm_fused_kernel(const __half* __restrict__ Ah, const __half* __restrict__ Al,
                       const __half* __restrict__ Bh, const __half* __restrict__ Bl,
                       const float* __restrict__ bias, float* __restrict__ C)
{
    constexpr int NCHUNK = KDIM / CH_K;

    extern __shared__ char smem[];
    const uint32_t tiles = (smem_u32(smem) + 1023u) & ~1023u;
    const int tid = threadIdx.x;
    const int lane = tid & 31, warp = tid >> 5;
    const int wm = warp & 1, wn = warp >> 1;     // 2 x 4 warp grid
    const int bx = blockIdx.x;                   // N tile
    const int by = blockIdx.y;                   // M tile

    const int lr  = tid >> 2;          // 0..63 (row)
    const int lcb = (tid & 3) * 16;    // byte col within 64B row

    const __half* Asrcs[2] = {Ah, Al};
    const __half* Bsrcs[2] = {Bh, Bl};

    auto issue_loads = [&](int chunk) {
        const int stage = chunk % 3;
        const uint32_t s = tiles + stage * ST_B;
        const int koff = chunk * CH_K + (lcb >> 1);
#pragma unroll
        for (int a = 0; a < 2; a++) {
            const __half* Ap = Asrcs[a] + (size_t)(by * 128 + lr) * KDIM + koff;
            const uint32_t d = s + a * TILE_B;
            CP_ASYNC16(d + swz64(lr * 64 + lcb), Ap);
            CP_ASYNC16(d + swz64((lr + 64) * 64 + lcb), Ap + (size_t)64 * KDIM);
        }
#pragma unroll
        for (int b = 0; b < 2; b++) {
            const __half* Bp = Bsrcs[b] + (size_t)(bx * 128 + lr) * KDIM + koff;
            const uint32_t d = s + (2 + b) * TILE_B;
            CP_ASYNC16(d + swz64(lr * 64 + lcb), Bp);
            CP_ASYNC16(d + swz64((lr + 64) * 64 + lcb), Bp + (size_t)64 * KDIM);
        }
    };

    float acc[4][4][4];
#pragma unroll
    for (int i = 0; i < 4; i++)
#pragma unroll
        for (int j = 0; j < 4; j++)
#pragma unroll
            for (int k = 0; k < 4; k++) acc[i][j][k] = 0.0f;

    const int lrow = lane & 15;
    const int lkof = (lane >> 4) * 16;

    issue_loads(0); CP_COMMIT();
    issue_loads(1); CP_COMMIT();

    for (int i = 0; i < NCHUNK; i++) {
        CP_WAIT1();
        __syncthreads();
        if (i + 2 < NCHUNK) issue_loads(i + 2);
        CP_COMMIT();

        const uint32_t s   = tiles + (i % 3) * ST_B;
        const uint32_t a_h = s;
        const uint32_t a_l = s + TILE_B;
        const uint32_t b_h = s + 2 * TILE_B;
        const uint32_t b_l = s + 3 * TILE_B;

#pragma unroll
        for (int ks = 0; ks < 2; ks++) {
            const int kb = ks * 32 + lkof;

            uint32_t bhf[4][2], blf[4][2];
#pragma unroll
            for (int bt = 0; bt < 2; bt++) {
                const int row = wn * 32 + bt * 16 + lrow;
                uint32_t r0, r1, r2, r3;
                ldsm_x4(r0, r1, r2, r3, b_l + swz64(row * 64 + kb));
                blf[bt * 2 + 0][0] = r0; blf[bt * 2 + 1][0] = r1;
                blf[bt * 2 + 0][1] = r2; blf[bt * 2 + 1][1] = r3;
                ldsm_x4(r0, r1, r2, r3, b_h + swz64(row * 64 + kb));
                bhf[bt * 2 + 0][0] = r0; bhf[bt * 2 + 1][0] = r1;
                bhf[bt * 2 + 0][1] = r2; bhf[bt * 2 + 1][1] = r3;
            }

#pragma unroll
            for (int mt = 0; mt < 4; mt++) {
                const int row = wm * 64 + mt * 16 + lrow;
                uint32_t ahf[4], alf[4];
                ldsm_x4(ahf[0], ahf[1], ahf[2], ahf[3],
                        a_h + swz64(row * 64 + kb));
                ldsm_x4(alf[0], alf[1], alf[2], alf[3],
                        a_l + swz64(row * 64 + kb));
#pragma unroll
                for (int nt = 0; nt < 4; nt++)
                    mma_f16(acc[mt][nt], ahf, blf[nt]);
#pragma unroll
                for (int nt = 0; nt < 4; nt++)
                    mma_f16(acc[mt][nt], alf, bhf[nt]);
#pragma unroll
                for (int nt = 0; nt < 4; nt++)
                    mma_f16(acc[mt][nt], ahf, bhf[nt]);
            }
        }
    }

    // ---- epilogue ----
    const int g = lane >> 2, t4 = lane & 3;
#pragma unroll
    for (int mt = 0; mt < 4; mt++) {
#pragma unroll
        for (int nt = 0; nt < 4; nt++) {
            const int rm = by * 128 + wm * 64 + mt * 16 + g;
            const int cg = bx * 128 + wn * 32 + nt * 8 + t4 * 2;
            const float b0 = __ldg(&bias[cg]);
            const float b1 = __ldg(&bias[cg + 1]);
            float v0 = acc[mt][nt][0] + b0;
            float v1 = acc[mt][nt][1] + b1;
            float v2 = acc[mt][nt][2] + b0;
            float v3 = acc[mt][nt][3] + b1;
            if (GELU) {
                v0 = 0.5f * v0 * (1.0f + erff(v0 * 0.70710678118654752f));
                v1 = 0.5f * v1 * (1.0f + erff(v1 * 0.70710678118654752f));
                v2 = 0.5f * v2 * (1.0f + erff(v2 * 0.70710678118654752f));
                v3 = 0.5f * v3 * (1.0f + erff(v3 * 0.70710678118654752f));
            }
            if (PERM) {
                const int nh = cg >> 8, ij = cg & 255;
                const int b_ = rm >> 11, t_ = rm & (TLEN - 1);
                float* o = C + (((size_t)(b_ * 16 + nh) * TLEN + t_) * 256 + ij);
                *(float2*)o = make_float2(v0, v1);
                *(float2*)(o + 8 * 256) = make_float2(v2, v3);
            } else {
                float* o = C + ((size_t)rm * NDIM + cg);
                *(float2*)o = make_float2(v0, v1);
                *(float2*)(o + (size_t)8 * NDIM) = make_float2(v2, v3);
            }
        }
    }
}

// ---------------------------------------------------------------------------
// Scan v4: DUAL-CHAIN interleaved. One warp runs BOTH directions (lr, rl) of
// one sequence with independent registers — while one chain stalls on its
// shfl-latency chain, the other issues. Ring slots hold both chains' matrices
// (2KB/slot). Per-chain math identical to v3 (rsqrt norm, rescale every 4th).
// Grid 128 x 32 threads.
// ---------------------------------------------------------------------------
#define SDEPTH 12

__global__ __launch_bounds__(32)
void scan_kernel(const float* __restrict__ mn, __half* __restrict__ xh,
                 __half* __restrict__ xl)
{
    __shared__ __align__(16) char ring[SDEPTH * 2048];

    const unsigned F = 0xffffffffu;
    const int lane = threadIdx.x & 31;
    const int s = blockIdx.x;              // sequence (b*16+nh), 0..127
    const int b = s >> 4;
    const int nh = s & 15;

    const uint32_t rb = smem_u32(ring);
    const uint32_t sw = (lane & 4) << 2;                 // 0 or 16
    const uint32_t o0 = ((uint32_t)lane * 32) ^ sw;
    const uint32_t o1 = ((uint32_t)lane * 32 + 16) ^ sw;

    const float* base = mn + (size_t)s * (TLEN * 256) + lane * 8;

    // lane l: row = l>>1, column half h = l&1 (cols h*8 .. h*8+7)
    const int h16 = (lane & 1) << 4;

    float u0 = (lane < 2) ? 1.0f : 0.0f;   // chain 0: lr  (t = step)
    float u1 = u0;                         // chain 1: rl  (t = 2047 - step)
    const size_t xoff0 = (size_t)b * TLEN * 512 + nh * 32 + (lane >> 1);
    const size_t xoff1 = xoff0 + 16;

    // prologue: fill 12 slots (both chains per slot; one commit group each)
#pragma unroll
    for (int j = 0; j < SDEPTH; j++) {
        const float* q0 = base + (size_t)j * 256;
        const float* q1 = base + (size_t)(TLEN - 1 - j) * 256;
        CP_ASYNC16(rb + j * 2048 + o0, q0);
        CP_ASYNC16(rb + j * 2048 + o1, q0 + 4);
        CP_ASYNC16(rb + j * 2048 + 1024 + o0, q1);
        CP_ASYNC16(rb + j * 2048 + 1024 + o1, q1 + 4);
        CP_COMMIT();
    }

    int slot = 0;
#pragma unroll 1
    for (int blk = 0; blk < TLEN / 4; ++blk) {
#pragma unroll
        for (int sub = 0; sub < 4; ++sub) {
            const int step = blk * 4 + sub;
            const int t0c = step;
            const int t1c = TLEN - 1 - step;

            CP_WAIT11();                       // slot's group complete

            const char* sl = ring + slot * 2048;
            const float4 a0 = *(const float4*)(sl + o0);
            const float4 a1 = *(const float4*)(sl + o1);
            const float4 b0 = *(const float4*)(sl + 1024 + o0);
            const float4 b1 = *(const float4*)(sl + 1024 + o1);

            // prefetch step+SDEPTH into this slot (clamped near the ends)
            int tp0 = t0c + SDEPTH; tp0 = tp0 > TLEN - 1 ? TLEN - 1 : tp0;
            int tp1 = t1c - SDEPTH; tp1 = tp1 < 0 ? 0 : tp1;
            const float* q0 = base + (size_t)tp0 * 256;
            const float* q1 = base + (size_t)tp1 * 256;
            CP_ASYNC16(rb + slot * 2048 + o0, q0);
            CP_ASYNC16(rb + slot * 2048 + o1, q0 + 4);
            CP_ASYNC16(rb + slot * 2048 + 1024 + o0, q1);
            CP_ASYNC16(rb + slot * 2048 + 1024 + o1, q1 + 4);
            CP_COMMIT();

            // ---- broadcasts (both chains interleaved; independent regs) ----
            const float c0v0 = __shfl_sync(F, u0, h16 + 0);
            const float c1v0 = __shfl_sync(F, u1, h16 + 0);
            const float c0v1 = __shfl_sync(F, u0, h16 + 2);
            const float c1v1 = __shfl_sync(F, u1, h16 + 2);
            const float c0v2 = __shfl_sync(F, u0, h16 + 4);
            const float c1v2 = __shfl_sync(F, u1, h16 + 4);
            const float c0v3 = __shfl_sync(F, u0, h16 + 6);
            const float c1v3 = __shfl_sync(F, u1, h16 + 6);
            const float c0v4 = __shfl_sync(F, u0, h16 + 8);
            const float c1v4 = __shfl_sync(F, u1, h16 + 8);
            const float c0v5 = __shfl_sync(F, u0, h16 + 10);
            const float c1v5 = __shfl_sync(F, u1, h16 + 10);
            const float c0v6 = __shfl_sync(F, u0, h16 + 12);
            const float c1v6 = __shfl_sync(F, u1, h16 + 12);
            const float c0v7 = __shfl_sync(F, u0, h16 + 14);
            const float c1v7 = __shfl_sync(F, u1, h16 + 14);

            // ---- matvec partials ----
            float p0A = a0.x * c0v0;
            float p1A = b0.x * c1v0;
            p0A = fmaf(a0.y, c0v1, p0A);
            p1A = fmaf(b0.y, c1v1, p1A);
            p0A = fmaf(a0.z, c0v2, p0A);
            p1A = fmaf(b0.z, c1v2, p1A);
            p0A = fmaf(a0.w, c0v3, p0A);
            p1A = fmaf(b0.w, c1v3, p1A);
            float p0B = a1.x * c0v4;
            float p1B = b1.x * c1v4;
            p0B = fmaf(a1.y, c0v5, p0B);
            p1B = fmaf(b1.y, c1v5, p1B);
            p0B = fmaf(a1.z, c0v6, p0B);
            p1B = fmaf(b1.z, c1v6, p1B);
            p0B = fmaf(a1.w, c0v7, p0B);
            p1B = fmaf(b1.w, c1v7, p1B);
            const float pp0 = p0A + p0B;
            const float pp1 = p1A + p1B;

            // pair-combine (lanes 2r, 2r+1 both get row r's value)
            const float nv0 = pp0 + __shfl_xor_sync(F, pp0, 1);
            const float nv1 = pp1 + __shfl_xor_sync(F, pp1, 1);

            // squared-norm reductions (interleaved)
            float ss0 = nv0 * nv0;
            float ss1 = nv1 * nv1;
            ss0 += __shfl_xor_sync(F, ss0, 2);
            ss1 += __shfl_xor_sync(F, ss1, 2);
            ss0 += __shfl_xor_sync(F, ss0, 4);
            ss1 += __shfl_xor_sync(F, ss1, 4);
            ss0 += __shfl_xor_sync(F, ss0, 8);
            ss1 += __shfl_xor_sync(F, ss1, 8);
            ss0 += __shfl_xor_sync(F, ss0, 16);
            ss1 += __shfl_xor_sync(F, ss1, 16);
            const float w0 = nv0 * rsqrtf(ss0 + 1e-12f);
            const float w1 = nv1 * rsqrtf(ss1 + 1e-12f);

            if ((lane & 1) == 0) {
                __half h0, l0, h1, l1;
                split_f16(w0, h0, l0);
                split_f16(w1, h1, l1);
                xh[xoff0 + (size_t)t0c * 512] = h0;
                xl[xoff0 + (size_t)t0c * 512] = l0;
                xh[xoff1 + (size_t)t1c * 512] = h1;
                xl[xoff1 + (size_t)t1c * 512] = l1;
            }

            // rescale every 4th step; other steps carry unnormalized nv
            u0 = (sub == 3) ? w0 : nv0;
            u1 = (sub == 3) ? w1 : nv1;

            if (++slot == SDEPTH) slot = 0;
        }
    }
}

// ---------------------------------------------------------------------------
// Launch
// ---------------------------------------------------------------------------
extern "C" void kernel_launch(void* const* d_in, const int* in_sizes, int n_in,
                              void* d_out, int out_size)
{
    const float* hs = (const float*)d_in[0];
    const float* Wm = (const float*)d_in[1];
    const float* bm = (const float*)d_in[2];
    const float* Wo = (const float*)d_in[3];
    const float* bo = (const float*)d_in[4];
    float* out = (float*)d_out;

    float* pm;
    __half *pah, *pal, *pbh, *pbl, *pxh, *pxl, *pwh, *pwl;
    cudaGetSymbolAddress((void**)&pm, g_m);
    cudaGetSymbolAddress((void**)&pah, g_ah);
    cudaGetSymbolAddress((void**)&pal, g_al);
    cudaGetSymbolAddress((void**)&pbh, g_bh);
    cudaGetSymbolAddress((void**)&pbl, g_bl);
    cudaGetSymbolAddress((void**)&pxh, g_xh);
    cudaGetSymbolAddress((void**)&pxl, g_xl);
    cudaGetSymbolAddress((void**)&pwh, g_wh);
    cudaGetSymbolAddress((void**)&pwl, g_wl);

    // 0) fp16 splits
    convA_kernel<<<(BT * HIDD / 4) / 256, 256>>>(hs, pah, pal);
    convW_kernel<<<dim3(N1 / 32, HIDD / 32), dim3(32, 32)>>>(Wm, pbh, pbl, HIDD, N1);
    convW_kernel<<<dim3(HIDD / 32, K2D / 32), dim3(32, 32)>>>(Wo, pwh, pwl, K2D, HIDD);

    // 1) GEMM1 fused-chunk -> scan layout (+bias), unnormalized
    cudaFuncSetAttribute(gemm_fused_kernel<true, false, HIDD, N1>,
                         cudaFuncAttributeMaxDynamicSharedMemorySize, G_SMEM);
    gemm_fused_kernel<true, false, HIDD, N1>
        <<<dim3(N1 / 128, BT / 128), 256, G_SMEM>>>(pah, pal, pbh, pbl, bm, pm);

    // 2) Bidirectional scan v4 (dual-chain interleaved) -> fp16 hi/lo
    scan_kernel<<<128, 32>>>(pm, pxh, pxl);

    // 3) GEMM2 fused-chunk: out = gelu(x @ W_out + b_out)
    cudaFuncSetAttribute(gemm_fused_kernel<false, true, K2D, HIDD>,
                         cudaFuncAttributeMaxDynamicSharedMemorySize, G_SMEM);
    gemm_fused_kernel<false, true, K2D, HIDD>
        <<<dim3(HIDD / 128, BT / 128), 256, G_SMEM>>>(pxh, pxl, pwh, pwl, bo, out);
}